// round 4
// baseline (speedup 1.0000x reference)
#include <cuda_runtime.h>
#include <math.h>

#define BGR 32768
#define NPG 54
#define EPG 144
#define GLOB 10
#define F0 8
#define F1 16
#define F2 4
#define CAT 226   /* 54*4 + 10 */
#define H1 128

// Scratch: concat([embeds, g]) per graph, [B, 226]
__device__ float g_emb[BGR * CAT];

// ---------------------------------------------------------------------------
// Kernel 1: per-graph GraphConv x2 (+ ReLU) and the global-feature MLP.
// One CTA (128 threads) per graph. Counting-sort CSR built once, reused by
// both conv layers so feature aggregation needs no atomics.
// ---------------------------------------------------------------------------
__global__ void __launch_bounds__(128) gconv_kernel(
    const float* __restrict__ x,
    const int*   __restrict__ eidx,    // [2, E]
    const float* __restrict__ eattr,
    const float* __restrict__ gfeat,
    const float* __restrict__ W_rel1, const float* __restrict__ b1,
    const float* __restrict__ W_root1,
    const float* __restrict__ W_rel2, const float* __restrict__ b2,
    const float* __restrict__ W_root2,
    const float* __restrict__ Wg1, const float* __restrict__ bg1,
    const float* __restrict__ Wg2, const float* __restrict__ bg2,
    const float* __restrict__ Wg3, const float* __restrict__ bg3)
{
    const int b   = blockIdx.x;
    const int tid = threadIdx.x;

    __shared__ float sx[NPG * F0];        // node features in
    __shared__ float sh[NPG * F1];        // conv1 output
    __shared__ float sagg[NPG * F1];      // aggregation scratch (reused)
    __shared__ float sattr_u[EPG];        // unsorted edge attr
    __shared__ short ssrc_u[EPG], sdst_u[EPG];
    __shared__ float sattr[EPG];          // dst-sorted edge attr
    __shared__ short ssrc[EPG];           // dst-sorted src
    __shared__ int   soff[NPG + 1];
    __shared__ int   scur[NPG];
    __shared__ float wr1[F0 * F1], wrt1[F0 * F1], sb1[F1];
    __shared__ float wr2[F1 * F2], wrt2[F1 * F2], sb2[F2];
    __shared__ float wg1[GLOB * 8], sbg1[8], wg2[64], sbg2[8], wg3[80], sbg3[GLOB];
    __shared__ float sgf[GLOB], sg1[8], sg2[8];

    // ---- loads (coalesced: each graph's x rows are contiguous) ----
    {
        const float4* xg = (const float4*)(x + (size_t)b * (NPG * F0));
        float4* sx4 = (float4*)sx;
        for (int i = tid; i < NPG * F0 / 4; i += 128) sx4[i] = xg[i];
    }
    {
        const int*   srcg = eidx + (size_t)b * EPG;
        const int*   dstg = eidx + (size_t)BGR * EPG + (size_t)b * EPG;
        const float* ag   = eattr + (size_t)b * EPG;
        const int base = b * NPG;
        for (int e = tid; e < EPG; e += 128) {
            ssrc_u[e]  = (short)(srcg[e] - base);
            sdst_u[e]  = (short)(dstg[e] - base);
            sattr_u[e] = ag[e];
        }
    }
    for (int i = tid; i < F0 * F1; i += 128) { wr1[i] = W_rel1[i]; wrt1[i] = W_root1[i]; }
    for (int i = tid; i < F1 * F2; i += 128) { wr2[i] = W_rel2[i]; wrt2[i] = W_root2[i]; }
    if (tid < F1) sb1[tid] = b1[tid];
    if (tid < F2) sb2[tid] = b2[tid];
    for (int i = tid; i < GLOB * 8; i += 128) wg1[i] = Wg1[i];
    if (tid < 64) wg2[tid] = Wg2[tid];
    if (tid < 80) wg3[tid] = Wg3[tid];
    if (tid < 8)  { sbg1[tid] = bg1[tid]; sbg2[tid] = bg2[tid]; }
    if (tid < GLOB) { sbg3[tid] = bg3[tid]; sgf[tid] = gfeat[(size_t)b * GLOB + tid]; }
    if (tid < NPG) scur[tid] = 0;
    __syncthreads();                                           // sync1

    // ---- counting sort phase A: degree counts (+ global-MLP layer 1) ----
    for (int e = tid; e < EPG; e += 128) atomicAdd(&scur[sdst_u[e]], 1);
    if (tid < 8) {
        float v = sbg1[tid];
        #pragma unroll
        for (int i = 0; i < GLOB; i++) v += sgf[i] * wg1[i * 8 + tid];
        sg1[tid] = fmaxf(v, 0.f);
    }
    __syncthreads();                                           // sync2

    // ---- prefix sum (+ global-MLP layer 2) ----
    if (tid == 0) {
        int acc = 0;
        for (int n = 0; n < NPG; n++) { soff[n] = acc; acc += scur[n]; }
        soff[NPG] = acc;
    }
    if (tid < 8) {
        float v = sbg2[tid];
        #pragma unroll
        for (int i = 0; i < 8; i++) v += sg1[i] * wg2[i * 8 + tid];
        sg2[tid] = fmaxf(v, 0.f);
    }
    __syncthreads();                                           // sync3
    if (tid < NPG) scur[tid] = soff[tid];
    __syncthreads();                                           // sync4

    // ---- scatter edges into CSR slots (+ global-MLP layer 3 writeout) ----
    for (int e = tid; e < EPG; e += 128) {
        int slot = atomicAdd(&scur[sdst_u[e]], 1);
        sattr[slot] = sattr_u[e];
        ssrc[slot]  = ssrc_u[e];
    }
    if (tid < GLOB) {
        float v = sbg3[tid];
        #pragma unroll
        for (int i = 0; i < 8; i++) v += sg2[i] * wg3[i * GLOB + tid];
        g_emb[(size_t)b * CAT + NPG * F2 + tid] = fmaxf(v, 0.f);
    }
    __syncthreads();                                           // sync5

    // ---- conv1 aggregation: sagg[:432] as [54][8], gather over CSR ----
    for (int it = tid; it < NPG * F0; it += 128) {
        int n = it >> 3, f = it & 7;
        float a = 0.f;
        int k0 = soff[n], k1 = soff[n + 1];
        for (int k = k0; k < k1; k++)
            a += sattr[k] * sx[(int)ssrc[k] * F0 + f];
        sagg[it] = a;
    }
    __syncthreads();

    // ---- conv1 linear + ReLU: sh = relu(agg@Wrel1 + b1 + x@Wroot1) ----
    for (int it = tid; it < NPG * F1; it += 128) {
        int n = it >> 4, j = it & 15;
        float v = sb1[j];
        #pragma unroll
        for (int i = 0; i < F0; i++)
            v += sagg[n * F0 + i] * wr1[i * F1 + j] + sx[n * F0 + i] * wrt1[i * F1 + j];
        sh[it] = fmaxf(v, 0.f);
    }
    __syncthreads();

    // ---- conv2 aggregation: sagg as [54][16] ----
    for (int it = tid; it < NPG * F1; it += 128) {
        int n = it >> 4, j = it & 15;
        float a = 0.f;
        int k0 = soff[n], k1 = soff[n + 1];
        for (int k = k0; k < k1; k++)
            a += sattr[k] * sh[(int)ssrc[k] * F1 + j];
        sagg[it] = a;
    }
    __syncthreads();

    // ---- conv2 linear + ReLU, write embeds [54*4] ----
    for (int it = tid; it < NPG * F2; it += 128) {
        int n = it >> 2, c = it & 3;
        float v = sb2[c];
        #pragma unroll
        for (int j = 0; j < F1; j++)
            v += sagg[n * F1 + j] * wr2[j * F2 + c] + sh[n * F1 + j] * wrt2[j * F2 + c];
        g_emb[(size_t)b * CAT + it] = fmaxf(v, 0.f);
    }
}

// ---------------------------------------------------------------------------
// Kernel 2: head.  out = sigmoid( relu(concat @ Wo1 + bo1) @ Wo2 + bo2 )
// Classic 128x128-tile SGEMM (K=226), epilogue fused: never materializes the
// [B,128] hidden layer.  Reduction buffer aliases the GEMM smem tiles to
// keep static smem small (16.5 KB -> 3 CTAs/SM).
// ---------------------------------------------------------------------------
__global__ void __launch_bounds__(256, 3) head_kernel(
    const float* __restrict__ Wo1, const float* __restrict__ bo1,
    const float* __restrict__ Wo2, const float* __restrict__ bo2,
    float* __restrict__ out)
{
    constexpr int BK = 16;
    // union: [0 .. 16*129) = As, [16*129 .. 16*129+16*128) = Bs;
    // after the GEMM loop the whole region is reused as red[128][17].
    __shared__ float smem[16 * 129 + 16 * 128];   // 16528 B; red needs 2176 floats
    float* As = smem;                // [BK][129]
    float* Bs = smem + 16 * 129;     // [BK][128]
    float* red = smem;               // [128][17] (8704 B)

    float acc[8][8];
    #pragma unroll
    for (int i = 0; i < 8; i++)
        #pragma unroll
        for (int j = 0; j < 8; j++) acc[i][j] = 0.f;

    const int rowBase = blockIdx.x * 128;
    const int tid = threadIdx.x;
    const int ty = tid >> 4, tx = tid & 15;
    const float* A = g_emb + (size_t)rowBase * CAT;

    for (int k0 = 0; k0 < CAT; k0 += BK) {
        #pragma unroll
        for (int l = 0; l < 8; l++) {
            int idx = tid + l * 256;
            int row = idx >> 4;
            int kk  = idx & 15;
            int k   = k0 + kk;
            As[kk * 129 + row] = (k < CAT) ? A[(size_t)row * CAT + k] : 0.f;
        }
        #pragma unroll
        for (int l = 0; l < 8; l++) {
            int idx = tid + l * 256;
            int kk  = idx >> 7;
            int col = idx & 127;
            int k   = k0 + kk;
            Bs[kk * 128 + col] = (k < CAT) ? Wo1[(size_t)k * H1 + col] : 0.f;
        }
        __syncthreads();
        #pragma unroll
        for (int kk = 0; kk < BK; kk++) {
            float a[8], bb[8];
            #pragma unroll
            for (int i = 0; i < 8; i++) a[i] = As[kk * 129 + ty * 8 + i];
            #pragma unroll
            for (int j = 0; j < 8; j++) bb[j] = Bs[kk * 128 + tx * 8 + j];
            #pragma unroll
            for (int i = 0; i < 8; i++)
                #pragma unroll
                for (int j = 0; j < 8; j++)
                    acc[i][j] += a[i] * bb[j];
        }
        __syncthreads();
    }

    // epilogue: bias + relu + dot with Wo2, partial per (row, tx)
    float w2[8], bb1[8];
    #pragma unroll
    for (int j = 0; j < 8; j++) { bb1[j] = bo1[tx * 8 + j]; w2[j] = Wo2[tx * 8 + j]; }
    #pragma unroll
    for (int i = 0; i < 8; i++) {
        float p = 0.f;
        #pragma unroll
        for (int j = 0; j < 8; j++) {
            float v = acc[i][j] + bb1[j];
            v = fmaxf(v, 0.f);
            p += v * w2[j];
        }
        red[(ty * 8 + i) * 17 + tx] = p;
    }
    __syncthreads();
    if (tid < 128) {
        float s = bo2[0];
        #pragma unroll
        for (int t = 0; t < 16; t++) s += red[tid * 17 + t];
        out[rowBase + tid] = 1.f / (1.f + expf(-s));
    }
}

extern "C" void kernel_launch(void* const* d_in, const int* in_sizes, int n_in,
                              void* d_out, int out_size)
{
    const float* x       = (const float*)d_in[0];
    const int*   eidx    = (const int*)  d_in[1];
    const float* eattr   = (const float*)d_in[2];
    const float* gfeat   = (const float*)d_in[3];
    const float* W_rel1  = (const float*)d_in[4];
    const float* b1      = (const float*)d_in[5];
    const float* W_root1 = (const float*)d_in[6];
    const float* W_rel2  = (const float*)d_in[7];
    const float* b2      = (const float*)d_in[8];
    const float* W_root2 = (const float*)d_in[9];
    const float* Wg1     = (const float*)d_in[10];
    const float* bg1     = (const float*)d_in[11];
    const float* Wg2     = (const float*)d_in[12];
    const float* bg2     = (const float*)d_in[13];
    const float* Wg3     = (const float*)d_in[14];
    const float* bg3     = (const float*)d_in[15];
    const float* Wo1     = (const float*)d_in[16];
    const float* bo1     = (const float*)d_in[17];
    const float* Wo2     = (const float*)d_in[18];
    const float* bo2     = (const float*)d_in[19];
    float* out = (float*)d_out;

    gconv_kernel<<<BGR, 128>>>(x, eidx, eattr, gfeat,
                               W_rel1, b1, W_root1,
                               W_rel2, b2, W_root2,
                               Wg1, bg1, Wg2, bg2, Wg3, bg3);
    head_kernel<<<BGR / 128, 256>>>(Wo1, bo1, Wo2, bo2, out);
}

// round 6
// speedup vs baseline: 2.3271x; 2.3271x over previous
#include <cuda_runtime.h>
#include <math.h>

#define BGR 32768
#define NPG 54
#define EPG 144
#define GLOB 10
#define F0 8
#define F1 16
#define F2 4
#define CAT 226   /* 54*4 + 10 */
#define H1 128
#define BM 64

// Scratch: concat([embeds, g]) per graph, [B, 226]
__device__ float g_emb[BGR * CAT];

// ---------------------------------------------------------------------------
// Kernel 1: per-graph GraphConv x2 (+ ReLU) and the global-feature MLP.
// One CTA (128 threads) per graph. Counting-sort CSR built once (warp-scan
// prefix sum), reused by both conv layers. All feature traffic is float4;
// sorted edges are packed {attr, src} float2; linear-layer weights live in
// registers (one smem load per CTA).
// ---------------------------------------------------------------------------
__global__ void __launch_bounds__(128) gconv_kernel(
    const float* __restrict__ x,
    const int*   __restrict__ eidx,    // [2, E]
    const float* __restrict__ eattr,
    const float* __restrict__ gfeat,
    const float* __restrict__ W_rel1, const float* __restrict__ b1,
    const float* __restrict__ W_root1,
    const float* __restrict__ W_rel2, const float* __restrict__ b2,
    const float* __restrict__ W_root2,
    const float* __restrict__ Wg1, const float* __restrict__ bg1,
    const float* __restrict__ Wg2, const float* __restrict__ bg2,
    const float* __restrict__ Wg3, const float* __restrict__ bg3)
{
    const int b   = blockIdx.x;
    const int tid = threadIdx.x;

    __shared__ float4 sx4[NPG * 2];       // x       [54][8]  as float4 pairs
    __shared__ float4 sh4[NPG * 4];       // conv1 out [54][16]
    __shared__ float4 sagg4[NPG * 4];     // agg scratch [54][16] (aliased early)
    __shared__ float2 sedge[EPG];         // dst-sorted {attr, src_as_float}
    __shared__ int    soff[NPG + 1];
    __shared__ int    scur[NPG];
    __shared__ int    wsum0;
    __shared__ float  wr1[F0 * F1], wrt1[F0 * F1], sb1[F1];
    __shared__ float  wr2[F1 * F2], wrt2[F1 * F2], sb2[F2];
    __shared__ float  wg1[GLOB * 8], wg2[64], wg3[80];
    __shared__ float  sbg1[8], sbg2[8], sbg3[GLOB], sgf[GLOB], sg1[8], sg2[8];

    // unsorted edge staging aliases sagg4 (unused until after scatter)
    float* sattr_u = (float*)sagg4;            // [144]
    short* ssrc_u  = (short*)(sattr_u + EPG);  // [144]
    short* sdst_u  = ssrc_u + EPG;             // [144]
    float* shf     = (float*)sh4;

    // ---- loads ----
    {
        const float4* xg = (const float4*)(x + (size_t)b * (NPG * F0));
        if (tid < NPG * 2) sx4[tid] = xg[tid];
    }
    {
        const int*   srcg = eidx + (size_t)b * EPG;
        const int*   dstg = eidx + (size_t)BGR * EPG + (size_t)b * EPG;
        const float* ag   = eattr + (size_t)b * EPG;
        const int base = b * NPG;
        for (int e = tid; e < EPG; e += 128) {
            ssrc_u[e]  = (short)(srcg[e] - base);
            sdst_u[e]  = (short)(dstg[e] - base);
            sattr_u[e] = ag[e];
        }
    }
    for (int i = tid; i < F0 * F1; i += 128) { wr1[i] = W_rel1[i]; wrt1[i] = W_root1[i]; }
    if (tid < F1 * F2) { wr2[tid] = W_rel2[tid]; wrt2[tid] = W_root2[tid]; }
    if (tid < F1) sb1[tid] = b1[tid];
    if (tid < F2) sb2[tid] = b2[tid];
    if (tid < GLOB * 8) wg1[tid] = Wg1[tid];
    if (tid < 64) wg2[tid] = Wg2[tid];
    if (tid < 80) wg3[tid] = Wg3[tid];
    if (tid < 8)  { sbg1[tid] = bg1[tid]; sbg2[tid] = bg2[tid]; }
    if (tid < GLOB) { sbg3[tid] = bg3[tid]; sgf[tid] = gfeat[(size_t)b * GLOB + tid]; }
    if (tid < NPG) scur[tid] = 0;
    __syncthreads();

    // ---- degree counts (+ global-MLP layer 1) ----
    for (int e = tid; e < EPG; e += 128) atomicAdd(&scur[sdst_u[e]], 1);
    if (tid < 8) {
        float v = sbg1[tid];
        #pragma unroll
        for (int i = 0; i < GLOB; i++) v += sgf[i] * wg1[i * 8 + tid];
        sg1[tid] = fmaxf(v, 0.f);
    }
    __syncthreads();

    // ---- warp-shuffle prefix scan over 54 counts (2 warps) ----
    if (tid < 64) {
        int c = (tid < NPG) ? scur[tid] : 0;
        int lane = tid & 31;
        int v = c;
        #pragma unroll
        for (int o = 1; o < 32; o <<= 1) {
            int u = __shfl_up_sync(0xffffffffu, v, o);
            if (lane >= o) v += u;
        }
        if (tid < NPG) soff[tid + 1] = v;
        if (tid == 31) wsum0 = v;
        if (tid == 0)  soff[0] = 0;
    }
    if (tid >= 64 && tid < 72) {   // global-MLP layer 2 on warp 2
        int j = tid - 64;
        float v = sbg2[j];
        #pragma unroll
        for (int i = 0; i < 8; i++) v += sg1[i] * wg2[i * 8 + j];
        sg2[j] = fmaxf(v, 0.f);
    }
    __syncthreads();
    if (tid >= 32 && tid < NPG) soff[tid + 1] += wsum0;
    __syncthreads();
    if (tid < NPG) scur[tid] = soff[tid];
    __syncthreads();

    // ---- scatter edges into CSR slots (+ global-MLP layer 3 writeout) ----
    for (int e = tid; e < EPG; e += 128) {
        int slot = atomicAdd(&scur[sdst_u[e]], 1);
        float2 pe; pe.x = sattr_u[e]; pe.y = __int_as_float((int)ssrc_u[e]);
        sedge[slot] = pe;
    }
    if (tid < GLOB) {
        float v = sbg3[tid];
        #pragma unroll
        for (int i = 0; i < 8; i++) v += sg2[i] * wg3[i * GLOB + tid];
        g_emb[(size_t)b * CAT + NPG * F2 + tid] = fmaxf(v, 0.f);
    }
    __syncthreads();   // sagg4 alias region dead after this -> reusable

    // ---- conv1 aggregation: one thread per (node, float4-half) ----
    if (tid < NPG * 2) {
        int n = tid >> 1, h = tid & 1;
        float4 a = make_float4(0.f, 0.f, 0.f, 0.f);
        int k1 = soff[n + 1];
        for (int k = soff[n]; k < k1; k++) {
            float2 e = sedge[k];
            float4 xv = sx4[__float_as_int(e.y) * 2 + h];
            a.x += e.x * xv.x; a.y += e.x * xv.y;
            a.z += e.x * xv.z; a.w += e.x * xv.w;
        }
        sagg4[tid] = a;    // layout [n][2]
    }
    __syncthreads();

    // ---- conv1 linear + ReLU: weights in regs, one column per thread ----
    {
        const int j = tid & 15, g = tid >> 4;   // g in 0..7
        float wc[16];
        const float bj = sb1[j];
        #pragma unroll
        for (int i = 0; i < F0; i++) { wc[i] = wr1[i * F1 + j]; wc[8 + i] = wrt1[i * F1 + j]; }
        for (int n = g; n < NPG; n += 8) {
            float4 a0 = sagg4[n * 2], a1 = sagg4[n * 2 + 1];
            float4 x0 = sx4[n * 2],  x1 = sx4[n * 2 + 1];
            float v = bj;
            v += a0.x * wc[0] + a0.y * wc[1] + a0.z * wc[2] + a0.w * wc[3];
            v += a1.x * wc[4] + a1.y * wc[5] + a1.z * wc[6] + a1.w * wc[7];
            v += x0.x * wc[8] + x0.y * wc[9] + x0.z * wc[10] + x0.w * wc[11];
            v += x1.x * wc[12] + x1.y * wc[13] + x1.z * wc[14] + x1.w * wc[15];
            shf[n * F1 + j] = fmaxf(v, 0.f);
        }
    }
    __syncthreads();

    // ---- conv2 aggregation: one thread per (node, float4-quarter) ----
    for (int it = tid; it < NPG * 4; it += 128) {
        int n = it >> 2, q = it & 3;
        float4 a = make_float4(0.f, 0.f, 0.f, 0.f);
        int k1 = soff[n + 1];
        for (int k = soff[n]; k < k1; k++) {
            float2 e = sedge[k];
            float4 hv = sh4[__float_as_int(e.y) * 4 + q];
            a.x += e.x * hv.x; a.y += e.x * hv.y;
            a.z += e.x * hv.z; a.w += e.x * hv.w;
        }
        sagg4[it] = a;     // layout [n][4]
    }
    __syncthreads();

    // ---- conv2 linear + ReLU, write embeds (coalesced STG) ----
    {
        const int c = tid & 3, g = tid >> 2;    // g in 0..31
        float wa[16], wb[16];
        #pragma unroll
        for (int j = 0; j < F1; j++) { wa[j] = wr2[j * F2 + c]; wb[j] = wrt2[j * F2 + c]; }
        const float bc = sb2[c];
        for (int n = g; n < NPG; n += 32) {
            float v = bc;
            #pragma unroll
            for (int q = 0; q < 4; q++) {
                float4 a = sagg4[n * 4 + q];
                float4 h = sh4[n * 4 + q];
                v += a.x * wa[q * 4 + 0] + a.y * wa[q * 4 + 1]
                   + a.z * wa[q * 4 + 2] + a.w * wa[q * 4 + 3];
                v += h.x * wb[q * 4 + 0] + h.y * wb[q * 4 + 1]
                   + h.z * wb[q * 4 + 2] + h.w * wb[q * 4 + 3];
            }
            g_emb[(size_t)b * CAT + n * F2 + c] = fmaxf(v, 0.f);
        }
    }
}

// ---------------------------------------------------------------------------
// Kernel 2: head.  out = sigmoid( relu(concat @ Wo1 + bo1) @ Wo2 + bo2 )
// 64x128 tile (grid=512 -> ~3.5 CTAs/SM), 256 threads, 4x8 microtile,
// fused epilogue (hidden layer never hits HBM).
// ---------------------------------------------------------------------------
__global__ void __launch_bounds__(256) head_kernel(
    const float* __restrict__ Wo1, const float* __restrict__ bo1,
    const float* __restrict__ Wo2, const float* __restrict__ bo2,
    float* __restrict__ out)
{
    constexpr int BK = 16;
    __shared__ __align__(16) float  As[BK][BM + 4];   // padded, float4-readable
    __shared__ float4 Bs4[BK][32];                    // [BK][128] floats
    __shared__ float  red[BM][17];

    const int rowBase = blockIdx.x * BM;
    const int tid = threadIdx.x;
    const int tx = tid & 15, ty = tid >> 4;           // ty 0..15

    float acc[4][8];
    #pragma unroll
    for (int i = 0; i < 4; i++)
        #pragma unroll
        for (int j = 0; j < 8; j++) acc[i][j] = 0.f;

    const float* A = g_emb + (size_t)rowBase * CAT;

    for (int k0 = 0; k0 < CAT; k0 += BK) {
        #pragma unroll
        for (int l = 0; l < 4; l++) {                 // A: 64x16 scalars
            int idx = tid + l * 256;
            int row = idx >> 4, kk = idx & 15;
            int k = k0 + kk;
            As[kk][row] = (k < CAT) ? A[(size_t)row * CAT + k] : 0.f;
        }
        #pragma unroll
        for (int l = 0; l < 2; l++) {                 // B: 16x128 via float4
            int idx = tid + l * 256;
            int kk = idx >> 5, c4 = idx & 31;
            int k = k0 + kk;
            Bs4[kk][c4] = (k < CAT) ? *(const float4*)&Wo1[(size_t)k * H1 + c4 * 4]
                                    : make_float4(0.f, 0.f, 0.f, 0.f);
        }
        __syncthreads();
        #pragma unroll
        for (int kk = 0; kk < BK; kk++) {
            float4 a  = *(const float4*)&As[kk][ty * 4];
            float4 b0 = Bs4[kk][tx * 2];
            float4 b1 = Bs4[kk][tx * 2 + 1];
            float av[4] = {a.x, a.y, a.z, a.w};
            float bv[8] = {b0.x, b0.y, b0.z, b0.w, b1.x, b1.y, b1.z, b1.w};
            #pragma unroll
            for (int i = 0; i < 4; i++)
                #pragma unroll
                for (int j = 0; j < 8; j++)
                    acc[i][j] += av[i] * bv[j];
        }
        __syncthreads();
    }

    // epilogue: bias + relu + dot(Wo2) partials, then cross-column reduce
    float bb[8], w2[8];
    #pragma unroll
    for (int j = 0; j < 8; j++) { bb[j] = bo1[tx * 8 + j]; w2[j] = Wo2[tx * 8 + j]; }
    #pragma unroll
    for (int i = 0; i < 4; i++) {
        float p = 0.f;
        #pragma unroll
        for (int j = 0; j < 8; j++) {
            float v = fmaxf(acc[i][j] + bb[j], 0.f);
            p += v * w2[j];
        }
        red[ty * 4 + i][tx] = p;
    }
    __syncthreads();
    if (tid < BM) {
        float s = bo2[0];
        #pragma unroll
        for (int t = 0; t < 16; t++) s += red[tid][t];
        out[rowBase + tid] = 1.f / (1.f + expf(-s));
    }
}

extern "C" void kernel_launch(void* const* d_in, const int* in_sizes, int n_in,
                              void* d_out, int out_size)
{
    const float* x       = (const float*)d_in[0];
    const int*   eidx    = (const int*)  d_in[1];
    const float* eattr   = (const float*)d_in[2];
    const float* gfeat   = (const float*)d_in[3];
    const float* W_rel1  = (const float*)d_in[4];
    const float* b1      = (const float*)d_in[5];
    const float* W_root1 = (const float*)d_in[6];
    const float* W_rel2  = (const float*)d_in[7];
    const float* b2      = (const float*)d_in[8];
    const float* W_root2 = (const float*)d_in[9];
    const float* Wg1     = (const float*)d_in[10];
    const float* bg1     = (const float*)d_in[11];
    const float* Wg2     = (const float*)d_in[12];
    const float* bg2     = (const float*)d_in[13];
    const float* Wg3     = (const float*)d_in[14];
    const float* bg3     = (const float*)d_in[15];
    const float* Wo1     = (const float*)d_in[16];
    const float* bo1     = (const float*)d_in[17];
    const float* Wo2     = (const float*)d_in[18];
    const float* bo2     = (const float*)d_in[19];
    float* out = (float*)d_out;

    gconv_kernel<<<BGR, 128>>>(x, eidx, eattr, gfeat,
                               W_rel1, b1, W_root1,
                               W_rel2, b2, W_root2,
                               Wg1, bg1, Wg2, bg2, Wg3, bg3);
    head_kernel<<<BGR / BM, 256>>>(Wo1, bo1, Wo2, bo2, out);
}